// round 14
// baseline (speedup 1.0000x reference)
#include <cuda_runtime.h>
#include <cuda_bf16.h>
#include <cstdint>

#define N_NODES 80000
#define N_EDGES 1280000
#define HID     64
#define MAXDEG  64

// ---------------- device scratch (no allocations allowed) ----------------
__device__ int   d_cnt[N_NODES];
__device__ __align__(16) int d_col[N_NODES * MAXDEG];   // fixed-width adjacency
__device__ __align__(16) float d_g[N_NODES * HID];      // GEMM out, fp32 natural order
__device__ __align__(16) float d_h[N_NODES * HID];      // agg out, fp32 natural order
__device__ float d_pooled[64 * 64];                     // per-graph SUMS (natural)
__device__ unsigned d_done;                             // aggpool completion counter

// ---------------- threefry-2x32 (JAX partitionable semantics) ----------------
__device__ __forceinline__ uint2 threefry_dev(unsigned k0, unsigned k1,
                                              unsigned c0, unsigned c1) {
    unsigned ks2 = k0 ^ k1 ^ 0x1BD11BDAu;
    unsigned x0 = c0 + k0, x1 = c1 + k1;
#define TF_RND(r) { x0 += x1; x1 = __funnelshift_l(x1, x1, (r)); x1 ^= x0; }
    TF_RND(13) TF_RND(15) TF_RND(26) TF_RND(6)   x0 += k1;  x1 += ks2 + 1u;
    TF_RND(17) TF_RND(29) TF_RND(16) TF_RND(24)  x0 += ks2; x1 += k0 + 2u;
    TF_RND(13) TF_RND(15) TF_RND(26) TF_RND(6)   x0 += k0;  x1 += k1 + 3u;
    TF_RND(17) TF_RND(29) TF_RND(16) TF_RND(24)  x0 += k1;  x1 += ks2 + 4u;
    TF_RND(13) TF_RND(15) TF_RND(26) TF_RND(6)   x0 += ks2; x1 += k0 + 5u;
#undef TF_RND
    return make_uint2(x0, x1);
}

// keep = u < 0.7f, exact integer form: bits < 5872026*512.
__device__ __forceinline__ bool keep_elem(unsigned k0, unsigned k1, unsigned idx) {
    uint2 r = threefry_dev(k0, k1, 0u, idx);
    return (r.x ^ r.y) < 3006477312u;
}

// ---------------- adjacency build: zero + direct scatter ----------------
__global__ void k_zero_cnt() {
    int i = blockIdx.x * 256 + threadIdx.x;
    if (i < N_NODES) d_cnt[i] = 0;
    if (i < 4096) d_pooled[i] = 0.0f;   // pool sums re-zeroed each replay
    if (i == 0) d_done = 0u;
}
__global__ void k_scatter(const int* __restrict__ ei) {
    int e = blockIdx.x * 256 + threadIdx.x;
    if (e < N_EDGES) {
        int src = ei[e];
        int dst = ei[N_EDGES + e];
        int pos = atomicAdd(&d_cnt[dst], 1);
        if (pos < MAXDEG) d_col[dst * MAXDEG + pos] = src;
    }
}

// ---------------- Layer-1 GEMM: g = X @ W1 (unscaled), fp32 natural ----------
__global__ void __launch_bounds__(128) k_gemm1(const float* __restrict__ X,
                                               const float* __restrict__ W) {
    __shared__ float  Xs[64][68];
    __shared__ float2 Ws[64][32];
    const int tid = threadIdx.x;
    const int rowBase = blockIdx.x * 64;
    const int tx = tid & 7, ty = tid >> 3;
    const int p0 = tx * 4, r0 = ty * 4;
    unsigned long long acc[4][4];
#pragma unroll
    for (int i = 0; i < 4; i++)
#pragma unroll
        for (int j = 0; j < 4; j++) acc[i][j] = 0ull;

    for (int kb = 0; kb < 128; kb += 64) {
#pragma unroll
        for (int t = 0; t < 32; t++) {
            int idx = tid + t * 128;
            int row = idx >> 6, kk = idx & 63;
            Xs[row][kk] = X[(size_t)(rowBase + row) * 128 + kb + kk];
        }
#pragma unroll
        for (int t = 0; t < 16; t++) {
            int idx = tid + t * 128;
            int kk = idx >> 5, p = idx & 31;
            int krow = kb + kk;
            Ws[kk][p] = make_float2(W[krow * 64 + 2 * p], W[krow * 64 + 2 * p + 1]);
        }
        __syncthreads();
#pragma unroll 8
        for (int kk = 0; kk < 64; ++kk) {
            ulonglong2 wA = *reinterpret_cast<const ulonglong2*>(&Ws[kk][p0]);
            ulonglong2 wB = *reinterpret_cast<const ulonglong2*>(&Ws[kk][p0 + 2]);
#pragma unroll
            for (int i = 0; i < 4; i++) {
                float x = Xs[r0 + i][kk];
                unsigned long long xp;
                asm("mov.b64 %0, {%1, %1};" : "=l"(xp) : "f"(x));
                asm("fma.rn.f32x2 %0, %1, %2, %0;" : "+l"(acc[i][0]) : "l"(xp), "l"(wA.x));
                asm("fma.rn.f32x2 %0, %1, %2, %0;" : "+l"(acc[i][1]) : "l"(xp), "l"(wA.y));
                asm("fma.rn.f32x2 %0, %1, %2, %0;" : "+l"(acc[i][2]) : "l"(xp), "l"(wB.x));
                asm("fma.rn.f32x2 %0, %1, %2, %0;" : "+l"(acc[i][3]) : "l"(xp), "l"(wB.y));
            }
        }
        __syncthreads();
    }
#pragma unroll
    for (int i = 0; i < 4; i++) {
        int row = rowBase + r0 + i;
        float f[8];
#pragma unroll
        for (int j = 0; j < 4; j++)
            asm("mov.b64 {%0, %1}, %2;" : "=f"(f[2 * j]), "=f"(f[2 * j + 1]) : "l"(acc[i][j]));
        *reinterpret_cast<float4*>(&d_g[row * 64 + 2 * p0]) =
            make_float4(f[0], f[1], f[2], f[3]);
        *reinterpret_cast<float4*>(&d_g[row * 64 + 2 * p0 + 4]) =
            make_float4(f[4], f[5], f[6], f[7]);
    }
}

// ---------------- Layer-2/3 GEMM: g = (d_h @ W) * dinv, fp32 natural ---------
__global__ void __launch_bounds__(128) k_gemm2(const float* __restrict__ W) {
    __shared__ float  Xs[64][68];
    __shared__ float2 Ws[64][32];
    const float* __restrict__ X = d_h;
    const int tid = threadIdx.x;
    const int rowBase = blockIdx.x * 64;
    const int tx = tid & 7, ty = tid >> 3;
    const int p0 = tx * 4, r0 = ty * 4;
    unsigned long long acc[4][4];
#pragma unroll
    for (int i = 0; i < 4; i++)
#pragma unroll
        for (int j = 0; j < 4; j++) acc[i][j] = 0ull;

#pragma unroll
    for (int t = 0; t < 32; t++) {
        int idx = tid + t * 128;
        int row = idx >> 6, kk = idx & 63;
        Xs[row][kk] = X[(size_t)(rowBase + row) * 64 + kk];
    }
#pragma unroll
    for (int t = 0; t < 16; t++) {
        int idx = tid + t * 128;
        int kk = idx >> 5, p = idx & 31;
        Ws[kk][p] = make_float2(W[kk * 64 + 2 * p], W[kk * 64 + 2 * p + 1]);
    }
    __syncthreads();
#pragma unroll 8
    for (int kk = 0; kk < 64; ++kk) {
        ulonglong2 wA = *reinterpret_cast<const ulonglong2*>(&Ws[kk][p0]);
        ulonglong2 wB = *reinterpret_cast<const ulonglong2*>(&Ws[kk][p0 + 2]);
#pragma unroll
        for (int i = 0; i < 4; i++) {
            float x = Xs[r0 + i][kk];
            unsigned long long xp;
            asm("mov.b64 %0, {%1, %1};" : "=l"(xp) : "f"(x));
            asm("fma.rn.f32x2 %0, %1, %2, %0;" : "+l"(acc[i][0]) : "l"(xp), "l"(wA.x));
            asm("fma.rn.f32x2 %0, %1, %2, %0;" : "+l"(acc[i][1]) : "l"(xp), "l"(wA.y));
            asm("fma.rn.f32x2 %0, %1, %2, %0;" : "+l"(acc[i][2]) : "l"(xp), "l"(wB.x));
            asm("fma.rn.f32x2 %0, %1, %2, %0;" : "+l"(acc[i][3]) : "l"(xp), "l"(wB.y));
        }
    }
#pragma unroll
    for (int i = 0; i < 4; i++) {
        int row = rowBase + r0 + i;
        float di = rsqrtf((float)d_cnt[row] + 1.0f);
        float f[8];
#pragma unroll
        for (int j = 0; j < 4; j++) {
            float lo, hi;
            asm("mov.b64 {%0, %1}, %2;" : "=f"(lo), "=f"(hi) : "l"(acc[i][j]));
            f[2 * j] = lo * di; f[2 * j + 1] = hi * di;
        }
        *reinterpret_cast<float4*>(&d_g[row * 64 + 2 * p0]) =
            make_float4(f[0], f[1], f[2], f[3]);
        *reinterpret_cast<float4*>(&d_g[row * 64 + 2 * p0 + 4]) =
            make_float4(f[4], f[5], f[6], f[7]);
    }
}

// ---------------- Aggregation + bias + ReLU + inline dropout (layers 1,2) ----
// 2 nodes per warp; index prefetch pipelines idx->feature dependency.
template <bool FIRST>
__global__ void __launch_bounds__(256) k_agg(const float* __restrict__ bias,
                                             unsigned k0, unsigned k1) {
    int gw = (blockIdx.x * 256 + threadIdx.x) >> 5;
    int lane = threadIdx.x & 31;
    int v = gw * 2 + (lane >> 4);
    int c0 = (lane & 15) * 4;

    int cntv = d_cnt[v];
    int deg = min(cntv, MAXDEG);
    float dv = rsqrtf((float)cntv + 1.0f);
    const int* __restrict__ cols = &d_col[(size_t)v * MAXDEG];

    float4 acc = *reinterpret_cast<const float4*>(&d_g[v * 64 + c0]);
    if (FIRST) { acc.x *= dv; acc.y *= dv; acc.z *= dv; acc.w *= dv; }

    int j = 0;
    if (deg >= 4) {
        int4 cur = *reinterpret_cast<const int4*>(&cols[0]);
        for (j = 4; j + 4 <= deg; j += 4) {
            int4 nxt = *reinterpret_cast<const int4*>(&cols[j]);   // prefetch
            float4 t0 = *reinterpret_cast<const float4*>(&d_g[cur.x * 64 + c0]);
            float4 t1 = *reinterpret_cast<const float4*>(&d_g[cur.y * 64 + c0]);
            float4 t2 = *reinterpret_cast<const float4*>(&d_g[cur.z * 64 + c0]);
            float4 t3 = *reinterpret_cast<const float4*>(&d_g[cur.w * 64 + c0]);
            if (FIRST) {
                float du0 = rsqrtf((float)d_cnt[cur.x] + 1.0f);
                float du1 = rsqrtf((float)d_cnt[cur.y] + 1.0f);
                float du2 = rsqrtf((float)d_cnt[cur.z] + 1.0f);
                float du3 = rsqrtf((float)d_cnt[cur.w] + 1.0f);
                acc.x = fmaf(t0.x, du0, acc.x); acc.y = fmaf(t0.y, du0, acc.y);
                acc.z = fmaf(t0.z, du0, acc.z); acc.w = fmaf(t0.w, du0, acc.w);
                acc.x = fmaf(t1.x, du1, acc.x); acc.y = fmaf(t1.y, du1, acc.y);
                acc.z = fmaf(t1.z, du1, acc.z); acc.w = fmaf(t1.w, du1, acc.w);
                acc.x = fmaf(t2.x, du2, acc.x); acc.y = fmaf(t2.y, du2, acc.y);
                acc.z = fmaf(t2.z, du2, acc.z); acc.w = fmaf(t2.w, du2, acc.w);
                acc.x = fmaf(t3.x, du3, acc.x); acc.y = fmaf(t3.y, du3, acc.y);
                acc.z = fmaf(t3.z, du3, acc.z); acc.w = fmaf(t3.w, du3, acc.w);
            } else {
                acc.x += (t0.x + t1.x) + (t2.x + t3.x);
                acc.y += (t0.y + t1.y) + (t2.y + t3.y);
                acc.z += (t0.z + t1.z) + (t2.z + t3.z);
                acc.w += (t0.w + t1.w) + (t2.w + t3.w);
            }
            cur = nxt;
        }
        {   // final full quad (cur)
            float4 t0 = *reinterpret_cast<const float4*>(&d_g[cur.x * 64 + c0]);
            float4 t1 = *reinterpret_cast<const float4*>(&d_g[cur.y * 64 + c0]);
            float4 t2 = *reinterpret_cast<const float4*>(&d_g[cur.z * 64 + c0]);
            float4 t3 = *reinterpret_cast<const float4*>(&d_g[cur.w * 64 + c0]);
            if (FIRST) {
                float du0 = rsqrtf((float)d_cnt[cur.x] + 1.0f);
                float du1 = rsqrtf((float)d_cnt[cur.y] + 1.0f);
                float du2 = rsqrtf((float)d_cnt[cur.z] + 1.0f);
                float du3 = rsqrtf((float)d_cnt[cur.w] + 1.0f);
                acc.x = fmaf(t0.x, du0, acc.x); acc.y = fmaf(t0.y, du0, acc.y);
                acc.z = fmaf(t0.z, du0, acc.z); acc.w = fmaf(t0.w, du0, acc.w);
                acc.x = fmaf(t1.x, du1, acc.x); acc.y = fmaf(t1.y, du1, acc.y);
                acc.z = fmaf(t1.z, du1, acc.z); acc.w = fmaf(t1.w, du1, acc.w);
                acc.x = fmaf(t2.x, du2, acc.x); acc.y = fmaf(t2.y, du2, acc.y);
                acc.z = fmaf(t2.z, du2, acc.z); acc.w = fmaf(t2.w, du2, acc.w);
                acc.x = fmaf(t3.x, du3, acc.x); acc.y = fmaf(t3.y, du3, acc.y);
                acc.z = fmaf(t3.z, du3, acc.z); acc.w = fmaf(t3.w, du3, acc.w);
            } else {
                acc.x += (t0.x + t1.x) + (t2.x + t3.x);
                acc.y += (t0.y + t1.y) + (t2.y + t3.y);
                acc.z += (t0.z + t1.z) + (t2.z + t3.z);
                acc.w += (t0.w + t1.w) + (t2.w + t3.w);
            }
        }
    }
    for (; j < deg; ++j) {
        int u = cols[j];
        float4 t = *reinterpret_cast<const float4*>(&d_g[u * 64 + c0]);
        if (FIRST) {
            float du = rsqrtf((float)d_cnt[u] + 1.0f);
            acc.x = fmaf(t.x, du, acc.x); acc.y = fmaf(t.y, du, acc.y);
            acc.z = fmaf(t.z, du, acc.z); acc.w = fmaf(t.w, du, acc.w);
        } else {
            acc.x += t.x; acc.y += t.y; acc.z += t.z; acc.w += t.w;
        }
    }

    float4 b4 = *reinterpret_cast<const float4*>(&bias[c0]);
    float o0 = fmaxf(fmaf(dv, acc.x, b4.x), 0.0f);
    float o1 = fmaxf(fmaf(dv, acc.y, b4.y), 0.0f);
    float o2 = fmaxf(fmaf(dv, acc.z, b4.z), 0.0f);
    float o3 = fmaxf(fmaf(dv, acc.w, b4.w), 0.0f);

    unsigned i0 = (unsigned)v * 64u + (unsigned)c0;
    const float inv_keep = 1.0f / 0.7f;
    float4 hv;
    hv.x = keep_elem(k0, k1, i0)      ? o0 * inv_keep : 0.0f;
    hv.y = keep_elem(k0, k1, i0 + 1u) ? o1 * inv_keep : 0.0f;
    hv.z = keep_elem(k0, k1, i0 + 2u) ? o2 * inv_keep : 0.0f;
    hv.w = keep_elem(k0, k1, i0 + 3u) ? o3 * inv_keep : 0.0f;
    *reinterpret_cast<float4*>(&d_h[v * 64 + c0]) = hv;
}

// ---------------- Layer-3 agg + pool + (last block) MLP head -----------------
__global__ void __launch_bounds__(256) k_aggpool(
        const float* __restrict__ bias, const int* __restrict__ batch,
        unsigned k0, unsigned k1,
        const float* __restrict__ Wm1, const float* __restrict__ bm1,
        const float* __restrict__ Wm2, const float* __restrict__ bm2,
        float* __restrict__ out, unsigned hk0, unsigned hk1) {
    __shared__ float accA[64], accB[64];
    __shared__ int gAB[2];
    int tid = threadIdx.x;
    if (tid < 64) accA[tid] = 0.0f;
    else if (tid < 128) accB[tid - 64] = 0.0f;
    int rowBase16 = blockIdx.x * 16;
    if (tid == 0) { gAB[0] = batch[rowBase16]; gAB[1] = batch[rowBase16 + 15]; }
    __syncthreads();

    int gw = (blockIdx.x * 256 + tid) >> 5;
    int lane = tid & 31;
    int v = gw * 2 + (lane >> 4);
    int c0 = (lane & 15) * 4;

    int cntv = d_cnt[v];
    int deg = min(cntv, MAXDEG);
    float dv = rsqrtf((float)cntv + 1.0f);
    const int* __restrict__ cols = &d_col[(size_t)v * MAXDEG];

    float4 acc = *reinterpret_cast<const float4*>(&d_g[v * 64 + c0]);
    int j = 0;
    if (deg >= 4) {
        int4 cur = *reinterpret_cast<const int4*>(&cols[0]);
        for (j = 4; j + 4 <= deg; j += 4) {
            int4 nxt = *reinterpret_cast<const int4*>(&cols[j]);
            float4 t0 = *reinterpret_cast<const float4*>(&d_g[cur.x * 64 + c0]);
            float4 t1 = *reinterpret_cast<const float4*>(&d_g[cur.y * 64 + c0]);
            float4 t2 = *reinterpret_cast<const float4*>(&d_g[cur.z * 64 + c0]);
            float4 t3 = *reinterpret_cast<const float4*>(&d_g[cur.w * 64 + c0]);
            acc.x += (t0.x + t1.x) + (t2.x + t3.x);
            acc.y += (t0.y + t1.y) + (t2.y + t3.y);
            acc.z += (t0.z + t1.z) + (t2.z + t3.z);
            acc.w += (t0.w + t1.w) + (t2.w + t3.w);
            cur = nxt;
        }
        float4 t0 = *reinterpret_cast<const float4*>(&d_g[cur.x * 64 + c0]);
        float4 t1 = *reinterpret_cast<const float4*>(&d_g[cur.y * 64 + c0]);
        float4 t2 = *reinterpret_cast<const float4*>(&d_g[cur.z * 64 + c0]);
        float4 t3 = *reinterpret_cast<const float4*>(&d_g[cur.w * 64 + c0]);
        acc.x += (t0.x + t1.x) + (t2.x + t3.x);
        acc.y += (t0.y + t1.y) + (t2.y + t3.y);
        acc.z += (t0.z + t1.z) + (t2.z + t3.z);
        acc.w += (t0.w + t1.w) + (t2.w + t3.w);
    }
    for (; j < deg; ++j) {
        int u = cols[j];
        float4 t = *reinterpret_cast<const float4*>(&d_g[u * 64 + c0]);
        acc.x += t.x; acc.y += t.y; acc.z += t.z; acc.w += t.w;
    }

    float4 b4 = *reinterpret_cast<const float4*>(&bias[c0]);
    float o0 = fmaxf(fmaf(dv, acc.x, b4.x), 0.0f);
    float o1 = fmaxf(fmaf(dv, acc.y, b4.y), 0.0f);
    float o2 = fmaxf(fmaf(dv, acc.z, b4.z), 0.0f);
    float o3 = fmaxf(fmaf(dv, acc.w, b4.w), 0.0f);

    unsigned i0 = (unsigned)v * 64u + (unsigned)c0;
    const float inv_keep = 1.0f / 0.7f;
    float h0 = keep_elem(k0, k1, i0)      ? o0 * inv_keep : 0.0f;
    float h1 = keep_elem(k0, k1, i0 + 1u) ? o1 * inv_keep : 0.0f;
    float h2 = keep_elem(k0, k1, i0 + 2u) ? o2 * inv_keep : 0.0f;
    float h3 = keep_elem(k0, k1, i0 + 3u) ? o3 * inv_keep : 0.0f;

    int g = batch[v];
    int gA = gAB[0], gB = gAB[1];
    if (g == gA) {
        atomicAdd(&accA[c0],     h0); atomicAdd(&accA[c0 + 1], h1);
        atomicAdd(&accA[c0 + 2], h2); atomicAdd(&accA[c0 + 3], h3);
    } else if (g == gB) {
        atomicAdd(&accB[c0],     h0); atomicAdd(&accB[c0 + 1], h1);
        atomicAdd(&accB[c0 + 2], h2); atomicAdd(&accB[c0 + 3], h3);
    } else {
        atomicAdd(&d_pooled[g * 64 + c0],     h0);
        atomicAdd(&d_pooled[g * 64 + c0 + 1], h1);
        atomicAdd(&d_pooled[g * 64 + c0 + 2], h2);
        atomicAdd(&d_pooled[g * 64 + c0 + 3], h3);
    }
    __syncthreads();
    if (tid < 64) atomicAdd(&d_pooled[gA * 64 + tid], accA[tid]);
    else if (tid < 128 && gAB[1] != gAB[0])
        atomicAdd(&d_pooled[gAB[1] * 64 + (tid - 64)], accB[tid - 64]);

    // ---- last-block-done: run the MLP head inline ----
    __threadfence();
    __shared__ bool amLast;
    if (tid == 0) amLast = (atomicAdd(&d_done, 1u) == gridDim.x - 1);
    __syncthreads();
    if (!amLast) return;

    __shared__ float Ps[64][64];
    __shared__ float Ws[64][64];
    __shared__ int   se[65];
    if (tid <= 64) {
        int target = tid;   // lower_bound(batch, target)
        int lo = 0, hi = N_NODES;
        while (lo < hi) { int m = (lo + hi) >> 1; if (batch[m] < target) lo = m + 1; else hi = m; }
        se[tid] = lo;
    }
    for (int idx = tid; idx < 4096; idx += 256)
        Ps[idx >> 6][idx & 63] = __ldcg(&d_pooled[idx]);   // L2 read (atomics landed there)
    for (int idx = tid; idx < 4096; idx += 256)
        Ws[idx >> 6][idx & 63] = Wm1[idx];
    __syncthreads();
    for (int idx = tid; idx < 4096; idx += 256) {
        int gg = idx >> 6;
        float cnt = fmaxf((float)(se[gg + 1] - se[gg]), 1.0f);
        Ps[gg][idx & 63] *= (1.0f / cnt);
    }
    __syncthreads();

    int c = tid & 63, gb = tid >> 6;       // gb in 0..3
    float m16[16];
#pragma unroll
    for (int ggi = 0; ggi < 16; ++ggi) {
        int gg = gb + ggi * 4;             // covers 0..63
        float mA = bm1[c];
#pragma unroll
        for (int s = 0; s < 64; s++) mA = fmaf(Ps[gg][s], Ws[s][c], mA);
        mA = fmaxf(mA, 0.0f);
        unsigned iH = (unsigned)gg * 64u + (unsigned)c;
        m16[ggi] = keep_elem(hk0, hk1, iH) ? mA * inv_keep : 0.0f;
    }
    __syncthreads();
#pragma unroll
    for (int ggi = 0; ggi < 16; ++ggi)
        Ps[gb + ggi * 4][c] = m16[ggi];
    __syncthreads();
    if (tid < 64) {
        float o = bm2[0];
#pragma unroll
        for (int cc = 0; cc < 64; ++cc) o = fmaf(Ps[tid][cc], Wm2[cc], o);
        out[tid] = o;
    }
}

// ---------------- host threefry (key splitting) ----------------
static inline void tf_host(unsigned k0, unsigned k1, unsigned c0, unsigned c1,
                           unsigned& o0, unsigned& o1) {
    unsigned ks2 = k0 ^ k1 ^ 0x1BD11BDAu;
    unsigned x0 = c0 + k0, x1 = c1 + k1;
#define HROT(x, r) (((x) << (r)) | ((x) >> (32 - (r))))
#define HRND(r) { x0 += x1; x1 = HROT(x1, r); x1 ^= x0; }
    HRND(13) HRND(15) HRND(26) HRND(6)   x0 += k1;  x1 += ks2 + 1u;
    HRND(17) HRND(29) HRND(16) HRND(24)  x0 += ks2; x1 += k0 + 2u;
    HRND(13) HRND(15) HRND(26) HRND(6)   x0 += k0;  x1 += k1 + 3u;
    HRND(17) HRND(29) HRND(16) HRND(24)  x0 += k1;  x1 += ks2 + 4u;
    HRND(13) HRND(15) HRND(26) HRND(6)   x0 += ks2; x1 += k0 + 5u;
#undef HRND
#undef HROT
    o0 = x0; o1 = x1;
}

extern "C" void kernel_launch(void* const* d_in, const int* in_sizes, int n_in,
                              void* d_out, int out_size) {
    const float* x     = (const float*)d_in[0];
    const int*   ei    = (const int*)d_in[1];
    const int*   batch = (const int*)d_in[2];
    const float* W1 = (const float*)d_in[3];  const float* b1 = (const float*)d_in[4];
    const float* W2 = (const float*)d_in[5];  const float* b2 = (const float*)d_in[6];
    const float* W3 = (const float*)d_in[7];  const float* b3 = (const float*)d_in[8];
    const float* Wm1 = (const float*)d_in[9]; const float* bm1 = (const float*)d_in[10];
    const float* Wm2 = (const float*)d_in[11];const float* bm2 = (const float*)d_in[12];
    float* out = (float*)d_out;

    // split(key(42), 4) partitionable: dk[i] = threefry((0,42), (0, i))
    unsigned dk[4][2];
    for (unsigned i = 0; i < 4; i++)
        tf_host(0u, 42u, 0u, i, dk[i][0], dk[i][1]);

    static cudaStream_t s_csr = nullptr;
    static cudaEvent_t ev_root = nullptr, ev_csr = nullptr;
    if (!s_csr) {
        cudaStreamCreateWithFlags(&s_csr, cudaStreamNonBlocking);
        cudaEventCreateWithFlags(&ev_root, cudaEventDisableTiming);
        cudaEventCreateWithFlags(&ev_csr, cudaEventDisableTiming);
    }

    const int NB64 = N_NODES / 64;                          // 1250
    const int AGG_BLOCKS = (N_NODES / 2 * 32 + 255) / 256;  // 5000

    cudaEventRecord(ev_root, (cudaStream_t)0);
    cudaStreamWaitEvent(s_csr, ev_root, 0);

    // Adjacency build (+ pool/counter zeroing) on side stream, overlapped with GEMM1.
    k_zero_cnt<<<(N_NODES + 255) / 256, 256, 0, s_csr>>>();
    k_scatter<<<(N_EDGES + 255) / 256, 256, 0, s_csr>>>(ei);
    cudaEventRecord(ev_csr, s_csr);

    k_gemm1<<<NB64, 128>>>(x, W1);

    cudaStreamWaitEvent((cudaStream_t)0, ev_csr, 0);

    k_agg<true><<<AGG_BLOCKS, 256>>>(b1, dk[0][0], dk[0][1]);
    k_gemm2<<<NB64, 128>>>(W2);
    k_agg<false><<<AGG_BLOCKS, 256>>>(b2, dk[1][0], dk[1][1]);
    k_gemm2<<<NB64, 128>>>(W3);
    k_aggpool<<<AGG_BLOCKS, 256>>>(b3, batch, dk[2][0], dk[2][1],
                                   Wm1, bm1, Wm2, bm2, out, dk[3][0], dk[3][1]);

    (void)in_sizes; (void)n_in; (void)out_size;
}

// round 15
// speedup vs baseline: 1.1956x; 1.1956x over previous
#include <cuda_runtime.h>
#include <cuda_bf16.h>
#include <cstdint>

#define N_NODES 80000
#define N_EDGES 1280000
#define HID     64
#define MAXDEG  64

// ---------------- device scratch (no allocations allowed) ----------------
__device__ int   d_cnt[N_NODES];
__device__ __align__(16) int d_col[N_NODES * MAXDEG];   // fixed-width adjacency
__device__ __align__(16) float d_g[N_NODES * HID];      // GEMM out, fp32 natural order
__device__ __align__(16) float d_h[N_NODES * HID];      // agg out, fp32 natural order
__device__ float d_pooled[64 * 64];                     // per-graph SUMS (natural)

// ---------------- threefry-2x32 (JAX partitionable semantics) ----------------
__device__ __forceinline__ uint2 threefry_dev(unsigned k0, unsigned k1,
                                              unsigned c0, unsigned c1) {
    unsigned ks2 = k0 ^ k1 ^ 0x1BD11BDAu;
    unsigned x0 = c0 + k0, x1 = c1 + k1;
#define TF_RND(r) { x0 += x1; x1 = __funnelshift_l(x1, x1, (r)); x1 ^= x0; }
    TF_RND(13) TF_RND(15) TF_RND(26) TF_RND(6)   x0 += k1;  x1 += ks2 + 1u;
    TF_RND(17) TF_RND(29) TF_RND(16) TF_RND(24)  x0 += ks2; x1 += k0 + 2u;
    TF_RND(13) TF_RND(15) TF_RND(26) TF_RND(6)   x0 += k0;  x1 += k1 + 3u;
    TF_RND(17) TF_RND(29) TF_RND(16) TF_RND(24)  x0 += k1;  x1 += ks2 + 4u;
    TF_RND(13) TF_RND(15) TF_RND(26) TF_RND(6)   x0 += ks2; x1 += k0 + 5u;
#undef TF_RND
    return make_uint2(x0, x1);
}

// keep = u < 0.7f, exact integer form: bits < 5872026*512.
__device__ __forceinline__ bool keep_elem(unsigned k0, unsigned k1, unsigned idx) {
    uint2 r = threefry_dev(k0, k1, 0u, idx);
    return (r.x ^ r.y) < 3006477312u;
}

// ---------------- adjacency build: zero + direct scatter ----------------
__global__ void k_zero_cnt() {
    int i = blockIdx.x * 256 + threadIdx.x;
    if (i < N_NODES) d_cnt[i] = 0;
    if (i < 4096) d_pooled[i] = 0.0f;   // pool sums re-zeroed each replay
}
__global__ void k_scatter(const int* __restrict__ ei) {
    int e = blockIdx.x * 256 + threadIdx.x;
    if (e < N_EDGES) {
        int src = ei[e];
        int dst = ei[N_EDGES + e];
        int pos = atomicAdd(&d_cnt[dst], 1);
        if (pos < MAXDEG) d_col[dst * MAXDEG + pos] = src;
    }
}

// ---------------- Layer-1 GEMM: g = X @ W1 (unscaled), fp32 natural ----------
__global__ void __launch_bounds__(128) k_gemm1(const float* __restrict__ X,
                                               const float* __restrict__ W) {
    __shared__ float  Xs[64][68];
    __shared__ float2 Ws[64][32];
    const int tid = threadIdx.x;
    const int rowBase = blockIdx.x * 64;
    const int tx = tid & 7, ty = tid >> 3;
    const int p0 = tx * 4, r0 = ty * 4;
    unsigned long long acc[4][4];
#pragma unroll
    for (int i = 0; i < 4; i++)
#pragma unroll
        for (int j = 0; j < 4; j++) acc[i][j] = 0ull;

    for (int kb = 0; kb < 128; kb += 64) {
#pragma unroll
        for (int t = 0; t < 32; t++) {
            int idx = tid + t * 128;
            int row = idx >> 6, kk = idx & 63;
            Xs[row][kk] = X[(size_t)(rowBase + row) * 128 + kb + kk];
        }
#pragma unroll
        for (int t = 0; t < 16; t++) {
            int idx = tid + t * 128;
            int kk = idx >> 5, p = idx & 31;
            int krow = kb + kk;
            Ws[kk][p] = make_float2(W[krow * 64 + 2 * p], W[krow * 64 + 2 * p + 1]);
        }
        __syncthreads();
#pragma unroll 8
        for (int kk = 0; kk < 64; ++kk) {
            ulonglong2 wA = *reinterpret_cast<const ulonglong2*>(&Ws[kk][p0]);
            ulonglong2 wB = *reinterpret_cast<const ulonglong2*>(&Ws[kk][p0 + 2]);
#pragma unroll
            for (int i = 0; i < 4; i++) {
                float x = Xs[r0 + i][kk];
                unsigned long long xp;
                asm("mov.b64 %0, {%1, %1};" : "=l"(xp) : "f"(x));
                asm("fma.rn.f32x2 %0, %1, %2, %0;" : "+l"(acc[i][0]) : "l"(xp), "l"(wA.x));
                asm("fma.rn.f32x2 %0, %1, %2, %0;" : "+l"(acc[i][1]) : "l"(xp), "l"(wA.y));
                asm("fma.rn.f32x2 %0, %1, %2, %0;" : "+l"(acc[i][2]) : "l"(xp), "l"(wB.x));
                asm("fma.rn.f32x2 %0, %1, %2, %0;" : "+l"(acc[i][3]) : "l"(xp), "l"(wB.y));
            }
        }
        __syncthreads();
    }
#pragma unroll
    for (int i = 0; i < 4; i++) {
        int row = rowBase + r0 + i;
        float f[8];
#pragma unroll
        for (int j = 0; j < 4; j++)
            asm("mov.b64 {%0, %1}, %2;" : "=f"(f[2 * j]), "=f"(f[2 * j + 1]) : "l"(acc[i][j]));
        *reinterpret_cast<float4*>(&d_g[row * 64 + 2 * p0]) =
            make_float4(f[0], f[1], f[2], f[3]);
        *reinterpret_cast<float4*>(&d_g[row * 64 + 2 * p0 + 4]) =
            make_float4(f[4], f[5], f[6], f[7]);
    }
}

// ---------------- Layer-2/3 GEMM: g = (d_h @ W) * dinv, fp32 natural ---------
__global__ void __launch_bounds__(128) k_gemm2(const float* __restrict__ W) {
    __shared__ float  Xs[64][68];
    __shared__ float2 Ws[64][32];
    const float* __restrict__ X = d_h;
    const int tid = threadIdx.x;
    const int rowBase = blockIdx.x * 64;
    const int tx = tid & 7, ty = tid >> 3;
    const int p0 = tx * 4, r0 = ty * 4;
    unsigned long long acc[4][4];
#pragma unroll
    for (int i = 0; i < 4; i++)
#pragma unroll
        for (int j = 0; j < 4; j++) acc[i][j] = 0ull;

#pragma unroll
    for (int t = 0; t < 32; t++) {
        int idx = tid + t * 128;
        int row = idx >> 6, kk = idx & 63;
        Xs[row][kk] = X[(size_t)(rowBase + row) * 64 + kk];
    }
#pragma unroll
    for (int t = 0; t < 16; t++) {
        int idx = tid + t * 128;
        int kk = idx >> 5, p = idx & 31;
        Ws[kk][p] = make_float2(W[kk * 64 + 2 * p], W[kk * 64 + 2 * p + 1]);
    }
    __syncthreads();
#pragma unroll 8
    for (int kk = 0; kk < 64; ++kk) {
        ulonglong2 wA = *reinterpret_cast<const ulonglong2*>(&Ws[kk][p0]);
        ulonglong2 wB = *reinterpret_cast<const ulonglong2*>(&Ws[kk][p0 + 2]);
#pragma unroll
        for (int i = 0; i < 4; i++) {
            float x = Xs[r0 + i][kk];
            unsigned long long xp;
            asm("mov.b64 %0, {%1, %1};" : "=l"(xp) : "f"(x));
            asm("fma.rn.f32x2 %0, %1, %2, %0;" : "+l"(acc[i][0]) : "l"(xp), "l"(wA.x));
            asm("fma.rn.f32x2 %0, %1, %2, %0;" : "+l"(acc[i][1]) : "l"(xp), "l"(wA.y));
            asm("fma.rn.f32x2 %0, %1, %2, %0;" : "+l"(acc[i][2]) : "l"(xp), "l"(wB.x));
            asm("fma.rn.f32x2 %0, %1, %2, %0;" : "+l"(acc[i][3]) : "l"(xp), "l"(wB.y));
        }
    }
#pragma unroll
    for (int i = 0; i < 4; i++) {
        int row = rowBase + r0 + i;
        float di = rsqrtf((float)d_cnt[row] + 1.0f);
        float f[8];
#pragma unroll
        for (int j = 0; j < 4; j++) {
            float lo, hi;
            asm("mov.b64 {%0, %1}, %2;" : "=f"(lo), "=f"(hi) : "l"(acc[i][j]));
            f[2 * j] = lo * di; f[2 * j + 1] = hi * di;
        }
        *reinterpret_cast<float4*>(&d_g[row * 64 + 2 * p0]) =
            make_float4(f[0], f[1], f[2], f[3]);
        *reinterpret_cast<float4*>(&d_g[row * 64 + 2 * p0 + 4]) =
            make_float4(f[4], f[5], f[6], f[7]);
    }
}

// ---------------- Aggregation + bias + ReLU + inline dropout (layers 1,2) ----
// 2 nodes per warp; index prefetch pipelines idx->feature dependency.
template <bool FIRST>
__global__ void __launch_bounds__(256) k_agg(const float* __restrict__ bias,
                                             unsigned k0, unsigned k1) {
    int gw = (blockIdx.x * 256 + threadIdx.x) >> 5;
    int lane = threadIdx.x & 31;
    int v = gw * 2 + (lane >> 4);
    int c0 = (lane & 15) * 4;

    int cntv = d_cnt[v];
    int deg = min(cntv, MAXDEG);
    float dv = rsqrtf((float)cntv + 1.0f);
    const int* __restrict__ cols = &d_col[(size_t)v * MAXDEG];

    float4 acc = *reinterpret_cast<const float4*>(&d_g[v * 64 + c0]);
    if (FIRST) { acc.x *= dv; acc.y *= dv; acc.z *= dv; acc.w *= dv; }

    int j = 0;
    if (deg >= 4) {
        int4 cur = *reinterpret_cast<const int4*>(&cols[0]);
        for (j = 4; j + 4 <= deg; j += 4) {
            int4 nxt = *reinterpret_cast<const int4*>(&cols[j]);   // prefetch
            float4 t0 = *reinterpret_cast<const float4*>(&d_g[cur.x * 64 + c0]);
            float4 t1 = *reinterpret_cast<const float4*>(&d_g[cur.y * 64 + c0]);
            float4 t2 = *reinterpret_cast<const float4*>(&d_g[cur.z * 64 + c0]);
            float4 t3 = *reinterpret_cast<const float4*>(&d_g[cur.w * 64 + c0]);
            if (FIRST) {
                float du0 = rsqrtf((float)d_cnt[cur.x] + 1.0f);
                float du1 = rsqrtf((float)d_cnt[cur.y] + 1.0f);
                float du2 = rsqrtf((float)d_cnt[cur.z] + 1.0f);
                float du3 = rsqrtf((float)d_cnt[cur.w] + 1.0f);
                acc.x = fmaf(t0.x, du0, acc.x); acc.y = fmaf(t0.y, du0, acc.y);
                acc.z = fmaf(t0.z, du0, acc.z); acc.w = fmaf(t0.w, du0, acc.w);
                acc.x = fmaf(t1.x, du1, acc.x); acc.y = fmaf(t1.y, du1, acc.y);
                acc.z = fmaf(t1.z, du1, acc.z); acc.w = fmaf(t1.w, du1, acc.w);
                acc.x = fmaf(t2.x, du2, acc.x); acc.y = fmaf(t2.y, du2, acc.y);
                acc.z = fmaf(t2.z, du2, acc.z); acc.w = fmaf(t2.w, du2, acc.w);
                acc.x = fmaf(t3.x, du3, acc.x); acc.y = fmaf(t3.y, du3, acc.y);
                acc.z = fmaf(t3.z, du3, acc.z); acc.w = fmaf(t3.w, du3, acc.w);
            } else {
                acc.x += (t0.x + t1.x) + (t2.x + t3.x);
                acc.y += (t0.y + t1.y) + (t2.y + t3.y);
                acc.z += (t0.z + t1.z) + (t2.z + t3.z);
                acc.w += (t0.w + t1.w) + (t2.w + t3.w);
            }
            cur = nxt;
        }
        {   // final full quad (cur)
            float4 t0 = *reinterpret_cast<const float4*>(&d_g[cur.x * 64 + c0]);
            float4 t1 = *reinterpret_cast<const float4*>(&d_g[cur.y * 64 + c0]);
            float4 t2 = *reinterpret_cast<const float4*>(&d_g[cur.z * 64 + c0]);
            float4 t3 = *reinterpret_cast<const float4*>(&d_g[cur.w * 64 + c0]);
            if (FIRST) {
                float du0 = rsqrtf((float)d_cnt[cur.x] + 1.0f);
                float du1 = rsqrtf((float)d_cnt[cur.y] + 1.0f);
                float du2 = rsqrtf((float)d_cnt[cur.z] + 1.0f);
                float du3 = rsqrtf((float)d_cnt[cur.w] + 1.0f);
                acc.x = fmaf(t0.x, du0, acc.x); acc.y = fmaf(t0.y, du0, acc.y);
                acc.z = fmaf(t0.z, du0, acc.z); acc.w = fmaf(t0.w, du0, acc.w);
                acc.x = fmaf(t1.x, du1, acc.x); acc.y = fmaf(t1.y, du1, acc.y);
                acc.z = fmaf(t1.z, du1, acc.z); acc.w = fmaf(t1.w, du1, acc.w);
                acc.x = fmaf(t2.x, du2, acc.x); acc.y = fmaf(t2.y, du2, acc.y);
                acc.z = fmaf(t2.z, du2, acc.z); acc.w = fmaf(t2.w, du2, acc.w);
                acc.x = fmaf(t3.x, du3, acc.x); acc.y = fmaf(t3.y, du3, acc.y);
                acc.z = fmaf(t3.z, du3, acc.z); acc.w = fmaf(t3.w, du3, acc.w);
            } else {
                acc.x += (t0.x + t1.x) + (t2.x + t3.x);
                acc.y += (t0.y + t1.y) + (t2.y + t3.y);
                acc.z += (t0.z + t1.z) + (t2.z + t3.z);
                acc.w += (t0.w + t1.w) + (t2.w + t3.w);
            }
        }
    }
    for (; j < deg; ++j) {
        int u = cols[j];
        float4 t = *reinterpret_cast<const float4*>(&d_g[u * 64 + c0]);
        if (FIRST) {
            float du = rsqrtf((float)d_cnt[u] + 1.0f);
            acc.x = fmaf(t.x, du, acc.x); acc.y = fmaf(t.y, du, acc.y);
            acc.z = fmaf(t.z, du, acc.z); acc.w = fmaf(t.w, du, acc.w);
        } else {
            acc.x += t.x; acc.y += t.y; acc.z += t.z; acc.w += t.w;
        }
    }

    float4 b4 = *reinterpret_cast<const float4*>(&bias[c0]);
    float o0 = fmaxf(fmaf(dv, acc.x, b4.x), 0.0f);
    float o1 = fmaxf(fmaf(dv, acc.y, b4.y), 0.0f);
    float o2 = fmaxf(fmaf(dv, acc.z, b4.z), 0.0f);
    float o3 = fmaxf(fmaf(dv, acc.w, b4.w), 0.0f);

    unsigned i0 = (unsigned)v * 64u + (unsigned)c0;
    const float inv_keep = 1.0f / 0.7f;
    float4 hv;
    hv.x = keep_elem(k0, k1, i0)      ? o0 * inv_keep : 0.0f;
    hv.y = keep_elem(k0, k1, i0 + 1u) ? o1 * inv_keep : 0.0f;
    hv.z = keep_elem(k0, k1, i0 + 2u) ? o2 * inv_keep : 0.0f;
    hv.w = keep_elem(k0, k1, i0 + 3u) ? o3 * inv_keep : 0.0f;
    *reinterpret_cast<float4*>(&d_h[v * 64 + c0]) = hv;
}

// ---------------- Layer-3 agg fused with mean-pool accumulation --------------
__global__ void __launch_bounds__(256) k_aggpool(const float* __restrict__ bias,
                                                 const int* __restrict__ batch,
                                                 unsigned k0, unsigned k1) {
    __shared__ float accA[64], accB[64];
    __shared__ int gAB[2];
    int tid = threadIdx.x;
    if (tid < 64) accA[tid] = 0.0f;
    else if (tid < 128) accB[tid - 64] = 0.0f;
    int rowBase16 = blockIdx.x * 16;
    if (tid == 0) { gAB[0] = batch[rowBase16]; gAB[1] = batch[rowBase16 + 15]; }
    __syncthreads();

    int gw = (blockIdx.x * 256 + tid) >> 5;
    int lane = tid & 31;
    int v = gw * 2 + (lane >> 4);
    int c0 = (lane & 15) * 4;

    int cntv = d_cnt[v];
    int deg = min(cntv, MAXDEG);
    float dv = rsqrtf((float)cntv + 1.0f);
    const int* __restrict__ cols = &d_col[(size_t)v * MAXDEG];

    float4 acc = *reinterpret_cast<const float4*>(&d_g[v * 64 + c0]);
    int j = 0;
    if (deg >= 4) {
        int4 cur = *reinterpret_cast<const int4*>(&cols[0]);
        for (j = 4; j + 4 <= deg; j += 4) {
            int4 nxt = *reinterpret_cast<const int4*>(&cols[j]);
            float4 t0 = *reinterpret_cast<const float4*>(&d_g[cur.x * 64 + c0]);
            float4 t1 = *reinterpret_cast<const float4*>(&d_g[cur.y * 64 + c0]);
            float4 t2 = *reinterpret_cast<const float4*>(&d_g[cur.z * 64 + c0]);
            float4 t3 = *reinterpret_cast<const float4*>(&d_g[cur.w * 64 + c0]);
            acc.x += (t0.x + t1.x) + (t2.x + t3.x);
            acc.y += (t0.y + t1.y) + (t2.y + t3.y);
            acc.z += (t0.z + t1.z) + (t2.z + t3.z);
            acc.w += (t0.w + t1.w) + (t2.w + t3.w);
            cur = nxt;
        }
        float4 t0 = *reinterpret_cast<const float4*>(&d_g[cur.x * 64 + c0]);
        float4 t1 = *reinterpret_cast<const float4*>(&d_g[cur.y * 64 + c0]);
        float4 t2 = *reinterpret_cast<const float4*>(&d_g[cur.z * 64 + c0]);
        float4 t3 = *reinterpret_cast<const float4*>(&d_g[cur.w * 64 + c0]);
        acc.x += (t0.x + t1.x) + (t2.x + t3.x);
        acc.y += (t0.y + t1.y) + (t2.y + t3.y);
        acc.z += (t0.z + t1.z) + (t2.z + t3.z);
        acc.w += (t0.w + t1.w) + (t2.w + t3.w);
    }
    for (; j < deg; ++j) {
        int u = cols[j];
        float4 t = *reinterpret_cast<const float4*>(&d_g[u * 64 + c0]);
        acc.x += t.x; acc.y += t.y; acc.z += t.z; acc.w += t.w;
    }

    float4 b4 = *reinterpret_cast<const float4*>(&bias[c0]);
    float o0 = fmaxf(fmaf(dv, acc.x, b4.x), 0.0f);
    float o1 = fmaxf(fmaf(dv, acc.y, b4.y), 0.0f);
    float o2 = fmaxf(fmaf(dv, acc.z, b4.z), 0.0f);
    float o3 = fmaxf(fmaf(dv, acc.w, b4.w), 0.0f);

    unsigned i0 = (unsigned)v * 64u + (unsigned)c0;
    const float inv_keep = 1.0f / 0.7f;
    float h0 = keep_elem(k0, k1, i0)      ? o0 * inv_keep : 0.0f;
    float h1 = keep_elem(k0, k1, i0 + 1u) ? o1 * inv_keep : 0.0f;
    float h2 = keep_elem(k0, k1, i0 + 2u) ? o2 * inv_keep : 0.0f;
    float h3 = keep_elem(k0, k1, i0 + 3u) ? o3 * inv_keep : 0.0f;

    int g = batch[v];
    int gA = gAB[0], gB = gAB[1];
    if (g == gA) {
        atomicAdd(&accA[c0],     h0); atomicAdd(&accA[c0 + 1], h1);
        atomicAdd(&accA[c0 + 2], h2); atomicAdd(&accA[c0 + 3], h3);
    } else if (g == gB) {
        atomicAdd(&accB[c0],     h0); atomicAdd(&accB[c0 + 1], h1);
        atomicAdd(&accB[c0 + 2], h2); atomicAdd(&accB[c0 + 3], h3);
    } else {
        atomicAdd(&d_pooled[g * 64 + c0],     h0);
        atomicAdd(&d_pooled[g * 64 + c0 + 1], h1);
        atomicAdd(&d_pooled[g * 64 + c0 + 2], h2);
        atomicAdd(&d_pooled[g * 64 + c0 + 3], h3);
    }
    __syncthreads();
    if (tid < 64) atomicAdd(&d_pooled[gA * 64 + tid], accA[tid]);
    else if (tid < 128 && gAB[1] != gAB[0])
        atomicAdd(&d_pooled[gAB[1] * 64 + (tid - 64)], accB[tid - 64]);
}

// ---------------- MLP head: normalize sums -> means, then Linear stack -------
__global__ void k_head(const int* __restrict__ batch,
                       const float* __restrict__ Wm1, const float* __restrict__ bm1,
                       const float* __restrict__ Wm2, const float* __restrict__ bm2,
                       float* __restrict__ out, unsigned k0, unsigned k1) {
    __shared__ float Ps[64][64];
    __shared__ float Ws[64][64];
    __shared__ int   se[65];
    int tid = threadIdx.x;
    if (tid <= 64) {
        int target = tid;
        int lo = 0, hi = N_NODES;
        while (lo < hi) { int m = (lo + hi) >> 1; if (batch[m] < target) lo = m + 1; else hi = m; }
        se[tid] = lo;
    }
    for (int idx = tid; idx < 4096; idx += 1024)
        Ps[idx >> 6][idx & 63] = d_pooled[idx];
    for (int idx = tid; idx < 4096; idx += 1024)
        Ws[idx >> 6][idx & 63] = Wm1[idx];
    __syncthreads();
    for (int idx = tid; idx < 4096; idx += 1024) {
        int g = idx >> 6;
        float cnt = fmaxf((float)(se[g + 1] - se[g]), 1.0f);
        Ps[g][idx & 63] *= (1.0f / cnt);
    }
    __syncthreads();

    int c = tid & 63, gb = tid >> 6;
    float mv[2][2];
#pragma unroll
    for (int halfg = 0; halfg < 2; ++halfg) {
        int g = gb + halfg * 16;
        float mA = bm1[c], mB = bm1[c];
#pragma unroll
        for (int s = 0; s < 64; s++) {
            mA = fmaf(Ps[g][s], Ws[s][c], mA);
            mB = fmaf(Ps[g + 32][s], Ws[s][c], mB);
        }
        mA = fmaxf(mA, 0.0f);
        mB = fmaxf(mB, 0.0f);
        unsigned iA = (unsigned)g * 64u + (unsigned)c;
        unsigned iB = (unsigned)(g + 32) * 64u + (unsigned)c;
        const float inv_keep = 1.0f / 0.7f;
        mv[halfg][0] = keep_elem(k0, k1, iA) ? mA * inv_keep : 0.0f;
        mv[halfg][1] = keep_elem(k0, k1, iB) ? mB * inv_keep : 0.0f;
    }
    __syncthreads();
#pragma unroll
    for (int halfg = 0; halfg < 2; ++halfg) {
        int g = gb + halfg * 16;
        Ps[g][c] = mv[halfg][0];
        Ps[g + 32][c] = mv[halfg][1];
    }
    __syncthreads();
    if (tid < 64) {
        float o = bm2[0];
#pragma unroll
        for (int cc = 0; cc < 64; ++cc) o = fmaf(Ps[tid][cc], Wm2[cc], o);
        out[tid] = o;
    }
}

// ---------------- host threefry (key splitting) ----------------
static inline void tf_host(unsigned k0, unsigned k1, unsigned c0, unsigned c1,
                           unsigned& o0, unsigned& o1) {
    unsigned ks2 = k0 ^ k1 ^ 0x1BD11BDAu;
    unsigned x0 = c0 + k0, x1 = c1 + k1;
#define HROT(x, r) (((x) << (r)) | ((x) >> (32 - (r))))
#define HRND(r) { x0 += x1; x1 = HROT(x1, r); x1 ^= x0; }
    HRND(13) HRND(15) HRND(26) HRND(6)   x0 += k1;  x1 += ks2 + 1u;
    HRND(17) HRND(29) HRND(16) HRND(24)  x0 += ks2; x1 += k0 + 2u;
    HRND(13) HRND(15) HRND(26) HRND(6)   x0 += k0;  x1 += k1 + 3u;
    HRND(17) HRND(29) HRND(16) HRND(24)  x0 += k1;  x1 += ks2 + 4u;
    HRND(13) HRND(15) HRND(26) HRND(6)   x0 += ks2; x1 += k0 + 5u;
#undef HRND
#undef HROT
    o0 = x0; o1 = x1;
}

extern "C" void kernel_launch(void* const* d_in, const int* in_sizes, int n_in,
                              void* d_out, int out_size) {
    const float* x     = (const float*)d_in[0];
    const int*   ei    = (const int*)d_in[1];
    const int*   batch = (const int*)d_in[2];
    const float* W1 = (const float*)d_in[3];  const float* b1 = (const float*)d_in[4];
    const float* W2 = (const float*)d_in[5];  const float* b2 = (const float*)d_in[6];
    const float* W3 = (const float*)d_in[7];  const float* b3 = (const float*)d_in[8];
    const float* Wm1 = (const float*)d_in[9]; const float* bm1 = (const float*)d_in[10];
    const float* Wm2 = (const float*)d_in[11];const float* bm2 = (const float*)d_in[12];
    float* out = (float*)d_out;

    // split(key(42), 4) partitionable: dk[i] = threefry((0,42), (0, i))
    unsigned dk[4][2];
    for (unsigned i = 0; i < 4; i++)
        tf_host(0u, 42u, 0u, i, dk[i][0], dk[i][1]);

    static cudaStream_t s_csr = nullptr;
    static cudaEvent_t ev_root = nullptr, ev_csr = nullptr;
    if (!s_csr) {
        cudaStreamCreateWithFlags(&s_csr, cudaStreamNonBlocking);
        cudaEventCreateWithFlags(&ev_root, cudaEventDisableTiming);
        cudaEventCreateWithFlags(&ev_csr, cudaEventDisableTiming);
    }

    const int NB64 = N_NODES / 64;                          // 1250
    const int AGG_BLOCKS = (N_NODES / 2 * 32 + 255) / 256;  // 5000

    cudaEventRecord(ev_root, (cudaStream_t)0);
    cudaStreamWaitEvent(s_csr, ev_root, 0);

    // Adjacency build (+ pool-sum zeroing) on side stream, overlapped with GEMM1.
    k_zero_cnt<<<(N_NODES + 255) / 256, 256, 0, s_csr>>>();
    k_scatter<<<(N_EDGES + 255) / 256, 256, 0, s_csr>>>(ei);
    cudaEventRecord(ev_csr, s_csr);

    k_gemm1<<<NB64, 128>>>(x, W1);

    cudaStreamWaitEvent((cudaStream_t)0, ev_csr, 0);

    k_agg<true><<<AGG_BLOCKS, 256>>>(b1, dk[0][0], dk[0][1]);
    k_gemm2<<<NB64, 128>>>(W2);
    k_agg<false><<<AGG_BLOCKS, 256>>>(b2, dk[1][0], dk[1][1]);
    k_gemm2<<<NB64, 128>>>(W3);
    k_aggpool<<<AGG_BLOCKS, 256>>>(b3, batch, dk[2][0], dk[2][1]);

    k_head<<<1, 1024>>>(batch, Wm1, bm1, Wm2, bm2, out, dk[3][0], dk[3][1]);

    (void)in_sizes; (void)n_in; (void)out_size;
}

// round 16
// speedup vs baseline: 1.2576x; 1.0518x over previous
#include <cuda_runtime.h>
#include <cuda_bf16.h>
#include <cstdint>

#define N_NODES 80000
#define N_EDGES 1280000
#define HID     64
#define MAXDEG  64

// ---------------- device scratch (no allocations allowed) ----------------
__device__ int   d_cnt[N_NODES];
__device__ float d_dinv[N_NODES];                       // rsqrt(cnt+1), precomputed
__device__ __align__(16) int d_col[N_NODES * MAXDEG];   // fixed-width adjacency
__device__ __align__(16) float d_g[N_NODES * HID];      // GEMM out, fp32 natural order
__device__ __align__(16) float d_h[N_NODES * HID];      // agg out, fp32 natural order
__device__ float d_pooled[64 * 64];                     // per-graph SUMS (natural)

// ---------------- threefry-2x32 (JAX partitionable semantics) ----------------
__device__ __forceinline__ uint2 threefry_dev(unsigned k0, unsigned k1,
                                              unsigned c0, unsigned c1) {
    unsigned ks2 = k0 ^ k1 ^ 0x1BD11BDAu;
    unsigned x0 = c0 + k0, x1 = c1 + k1;
#define TF_RND(r) { x0 += x1; x1 = __funnelshift_l(x1, x1, (r)); x1 ^= x0; }
    TF_RND(13) TF_RND(15) TF_RND(26) TF_RND(6)   x0 += k1;  x1 += ks2 + 1u;
    TF_RND(17) TF_RND(29) TF_RND(16) TF_RND(24)  x0 += ks2; x1 += k0 + 2u;
    TF_RND(13) TF_RND(15) TF_RND(26) TF_RND(6)   x0 += k0;  x1 += k1 + 3u;
    TF_RND(17) TF_RND(29) TF_RND(16) TF_RND(24)  x0 += k1;  x1 += ks2 + 4u;
    TF_RND(13) TF_RND(15) TF_RND(26) TF_RND(6)   x0 += ks2; x1 += k0 + 5u;
#undef TF_RND
    return make_uint2(x0, x1);
}

// keep = u < 0.7f, exact integer form: bits < 5872026*512.
__device__ __forceinline__ bool keep_elem(unsigned k0, unsigned k1, unsigned idx) {
    uint2 r = threefry_dev(k0, k1, 0u, idx);
    return (r.x ^ r.y) < 3006477312u;
}

// ---------------- adjacency build: zero + direct scatter + dinv ----------------
__global__ void k_zero_cnt() {
    int i = blockIdx.x * 256 + threadIdx.x;
    if (i < N_NODES) d_cnt[i] = 0;
    if (i < 4096) d_pooled[i] = 0.0f;   // pool sums re-zeroed each replay
}
__global__ void k_scatter(const int* __restrict__ ei) {
    int e = blockIdx.x * 256 + threadIdx.x;
    if (e < N_EDGES) {
        int src = ei[e];
        int dst = ei[N_EDGES + e];
        int pos = atomicAdd(&d_cnt[dst], 1);
        if (pos < MAXDEG) d_col[dst * MAXDEG + pos] = src;
    }
}
__global__ void k_dinv() {
    int i = blockIdx.x * 256 + threadIdx.x;
    if (i < N_NODES) d_dinv[i] = rsqrtf((float)d_cnt[i] + 1.0f);
}

// ---------------- Layer-1 GEMM: g = X @ W1 (unscaled), fp32 natural ----------
__global__ void __launch_bounds__(128) k_gemm1(const float* __restrict__ X,
                                               const float* __restrict__ W) {
    __shared__ float  Xs[64][68];
    __shared__ float2 Ws[64][32];
    const int tid = threadIdx.x;
    const int rowBase = blockIdx.x * 64;
    const int tx = tid & 7, ty = tid >> 3;
    const int p0 = tx * 4, r0 = ty * 4;
    unsigned long long acc[4][4];
#pragma unroll
    for (int i = 0; i < 4; i++)
#pragma unroll
        for (int j = 0; j < 4; j++) acc[i][j] = 0ull;

    for (int kb = 0; kb < 128; kb += 64) {
#pragma unroll
        for (int t = 0; t < 32; t++) {
            int idx = tid + t * 128;
            int row = idx >> 6, kk = idx & 63;
            Xs[row][kk] = X[(size_t)(rowBase + row) * 128 + kb + kk];
        }
#pragma unroll
        for (int t = 0; t < 16; t++) {
            int idx = tid + t * 128;
            int kk = idx >> 5, p = idx & 31;
            int krow = kb + kk;
            Ws[kk][p] = make_float2(W[krow * 64 + 2 * p], W[krow * 64 + 2 * p + 1]);
        }
        __syncthreads();
#pragma unroll 8
        for (int kk = 0; kk < 64; ++kk) {
            ulonglong2 wA = *reinterpret_cast<const ulonglong2*>(&Ws[kk][p0]);
            ulonglong2 wB = *reinterpret_cast<const ulonglong2*>(&Ws[kk][p0 + 2]);
#pragma unroll
            for (int i = 0; i < 4; i++) {
                float x = Xs[r0 + i][kk];
                unsigned long long xp;
                asm("mov.b64 %0, {%1, %1};" : "=l"(xp) : "f"(x));
                asm("fma.rn.f32x2 %0, %1, %2, %0;" : "+l"(acc[i][0]) : "l"(xp), "l"(wA.x));
                asm("fma.rn.f32x2 %0, %1, %2, %0;" : "+l"(acc[i][1]) : "l"(xp), "l"(wA.y));
                asm("fma.rn.f32x2 %0, %1, %2, %0;" : "+l"(acc[i][2]) : "l"(xp), "l"(wB.x));
                asm("fma.rn.f32x2 %0, %1, %2, %0;" : "+l"(acc[i][3]) : "l"(xp), "l"(wB.y));
            }
        }
        __syncthreads();
    }
#pragma unroll
    for (int i = 0; i < 4; i++) {
        int row = rowBase + r0 + i;
        float f[8];
#pragma unroll
        for (int j = 0; j < 4; j++)
            asm("mov.b64 {%0, %1}, %2;" : "=f"(f[2 * j]), "=f"(f[2 * j + 1]) : "l"(acc[i][j]));
        *reinterpret_cast<float4*>(&d_g[row * 64 + 2 * p0]) =
            make_float4(f[0], f[1], f[2], f[3]);
        *reinterpret_cast<float4*>(&d_g[row * 64 + 2 * p0 + 4]) =
            make_float4(f[4], f[5], f[6], f[7]);
    }
}

// ---------------- Layer-2/3 GEMM: g = (d_h @ W) * dinv, fp32 natural ---------
__global__ void __launch_bounds__(128) k_gemm2(const float* __restrict__ W) {
    __shared__ float  Xs[64][68];
    __shared__ float2 Ws[64][32];
    const float* __restrict__ X = d_h;
    const int tid = threadIdx.x;
    const int rowBase = blockIdx.x * 64;
    const int tx = tid & 7, ty = tid >> 3;
    const int p0 = tx * 4, r0 = ty * 4;
    unsigned long long acc[4][4];
#pragma unroll
    for (int i = 0; i < 4; i++)
#pragma unroll
        for (int j = 0; j < 4; j++) acc[i][j] = 0ull;

#pragma unroll
    for (int t = 0; t < 32; t++) {
        int idx = tid + t * 128;
        int row = idx >> 6, kk = idx & 63;
        Xs[row][kk] = X[(size_t)(rowBase + row) * 64 + kk];
    }
#pragma unroll
    for (int t = 0; t < 16; t++) {
        int idx = tid + t * 128;
        int kk = idx >> 5, p = idx & 31;
        Ws[kk][p] = make_float2(W[kk * 64 + 2 * p], W[kk * 64 + 2 * p + 1]);
    }
    __syncthreads();
#pragma unroll 8
    for (int kk = 0; kk < 64; ++kk) {
        ulonglong2 wA = *reinterpret_cast<const ulonglong2*>(&Ws[kk][p0]);
        ulonglong2 wB = *reinterpret_cast<const ulonglong2*>(&Ws[kk][p0 + 2]);
#pragma unroll
        for (int i = 0; i < 4; i++) {
            float x = Xs[r0 + i][kk];
            unsigned long long xp;
            asm("mov.b64 %0, {%1, %1};" : "=l"(xp) : "f"(x));
            asm("fma.rn.f32x2 %0, %1, %2, %0;" : "+l"(acc[i][0]) : "l"(xp), "l"(wA.x));
            asm("fma.rn.f32x2 %0, %1, %2, %0;" : "+l"(acc[i][1]) : "l"(xp), "l"(wA.y));
            asm("fma.rn.f32x2 %0, %1, %2, %0;" : "+l"(acc[i][2]) : "l"(xp), "l"(wB.x));
            asm("fma.rn.f32x2 %0, %1, %2, %0;" : "+l"(acc[i][3]) : "l"(xp), "l"(wB.y));
        }
    }
#pragma unroll
    for (int i = 0; i < 4; i++) {
        int row = rowBase + r0 + i;
        float di = d_dinv[row];
        float f[8];
#pragma unroll
        for (int j = 0; j < 4; j++) {
            float lo, hi;
            asm("mov.b64 {%0, %1}, %2;" : "=f"(lo), "=f"(hi) : "l"(acc[i][j]));
            f[2 * j] = lo * di; f[2 * j + 1] = hi * di;
        }
        *reinterpret_cast<float4*>(&d_g[row * 64 + 2 * p0]) =
            make_float4(f[0], f[1], f[2], f[3]);
        *reinterpret_cast<float4*>(&d_g[row * 64 + 2 * p0 + 4]) =
            make_float4(f[4], f[5], f[6], f[7]);
    }
}

// ---------------- Aggregation + bias + ReLU + inline dropout (layers 1,2) ----
// R12 proven body; only change: per-edge dinv is a direct load (no rsqrt chain).
template <bool FIRST>
__global__ void __launch_bounds__(256) k_agg(const float* __restrict__ bias,
                                             unsigned k0, unsigned k1) {
    int gw = (blockIdx.x * 256 + threadIdx.x) >> 5;
    int lane = threadIdx.x & 31;
    int v = gw * 2 + (lane >> 4);
    int c0 = (lane & 15) * 4;

    int deg = min(d_cnt[v], MAXDEG);
    float dv = d_dinv[v];
    const int* __restrict__ cols = &d_col[(size_t)v * MAXDEG];

    float4 acc = *reinterpret_cast<const float4*>(&d_g[v * 64 + c0]);
    if (FIRST) { acc.x *= dv; acc.y *= dv; acc.z *= dv; acc.w *= dv; }

    int j = 0;
    for (; j + 4 <= deg; j += 4) {
        int4 c4 = *reinterpret_cast<const int4*>(&cols[j]);
        float4 t0 = *reinterpret_cast<const float4*>(&d_g[c4.x * 64 + c0]);
        float4 t1 = *reinterpret_cast<const float4*>(&d_g[c4.y * 64 + c0]);
        float4 t2 = *reinterpret_cast<const float4*>(&d_g[c4.z * 64 + c0]);
        float4 t3 = *reinterpret_cast<const float4*>(&d_g[c4.w * 64 + c0]);
        if (FIRST) {
            float du0 = d_dinv[c4.x];
            float du1 = d_dinv[c4.y];
            float du2 = d_dinv[c4.z];
            float du3 = d_dinv[c4.w];
            acc.x = fmaf(t0.x, du0, acc.x); acc.y = fmaf(t0.y, du0, acc.y);
            acc.z = fmaf(t0.z, du0, acc.z); acc.w = fmaf(t0.w, du0, acc.w);
            acc.x = fmaf(t1.x, du1, acc.x); acc.y = fmaf(t1.y, du1, acc.y);
            acc.z = fmaf(t1.z, du1, acc.z); acc.w = fmaf(t1.w, du1, acc.w);
            acc.x = fmaf(t2.x, du2, acc.x); acc.y = fmaf(t2.y, du2, acc.y);
            acc.z = fmaf(t2.z, du2, acc.z); acc.w = fmaf(t2.w, du2, acc.w);
            acc.x = fmaf(t3.x, du3, acc.x); acc.y = fmaf(t3.y, du3, acc.y);
            acc.z = fmaf(t3.z, du3, acc.z); acc.w = fmaf(t3.w, du3, acc.w);
        } else {
            acc.x += (t0.x + t1.x) + (t2.x + t3.x);
            acc.y += (t0.y + t1.y) + (t2.y + t3.y);
            acc.z += (t0.z + t1.z) + (t2.z + t3.z);
            acc.w += (t0.w + t1.w) + (t2.w + t3.w);
        }
    }
    for (; j < deg; ++j) {
        int u = cols[j];
        float4 t = *reinterpret_cast<const float4*>(&d_g[u * 64 + c0]);
        if (FIRST) {
            float du = d_dinv[u];
            acc.x = fmaf(t.x, du, acc.x); acc.y = fmaf(t.y, du, acc.y);
            acc.z = fmaf(t.z, du, acc.z); acc.w = fmaf(t.w, du, acc.w);
        } else {
            acc.x += t.x; acc.y += t.y; acc.z += t.z; acc.w += t.w;
        }
    }

    float4 b4 = *reinterpret_cast<const float4*>(&bias[c0]);
    float o0 = fmaxf(fmaf(dv, acc.x, b4.x), 0.0f);
    float o1 = fmaxf(fmaf(dv, acc.y, b4.y), 0.0f);
    float o2 = fmaxf(fmaf(dv, acc.z, b4.z), 0.0f);
    float o3 = fmaxf(fmaf(dv, acc.w, b4.w), 0.0f);

    unsigned i0 = (unsigned)v * 64u + (unsigned)c0;
    const float inv_keep = 1.0f / 0.7f;
    float4 hv;
    hv.x = keep_elem(k0, k1, i0)      ? o0 * inv_keep : 0.0f;
    hv.y = keep_elem(k0, k1, i0 + 1u) ? o1 * inv_keep : 0.0f;
    hv.z = keep_elem(k0, k1, i0 + 2u) ? o2 * inv_keep : 0.0f;
    hv.w = keep_elem(k0, k1, i0 + 3u) ? o3 * inv_keep : 0.0f;
    *reinterpret_cast<float4*>(&d_h[v * 64 + c0]) = hv;
}

// ---------------- Layer-3 agg fused with mean-pool accumulation --------------
__global__ void __launch_bounds__(256) k_aggpool(const float* __restrict__ bias,
                                                 const int* __restrict__ batch,
                                                 unsigned k0, unsigned k1) {
    __shared__ float accA[64], accB[64];
    __shared__ int gAB[2];
    int tid = threadIdx.x;
    if (tid < 64) accA[tid] = 0.0f;
    else if (tid < 128) accB[tid - 64] = 0.0f;
    int rowBase16 = blockIdx.x * 16;
    if (tid == 0) { gAB[0] = batch[rowBase16]; gAB[1] = batch[rowBase16 + 15]; }
    __syncthreads();

    int gw = (blockIdx.x * 256 + tid) >> 5;
    int lane = tid & 31;
    int v = gw * 2 + (lane >> 4);
    int c0 = (lane & 15) * 4;

    int deg = min(d_cnt[v], MAXDEG);
    float dv = d_dinv[v];
    const int* __restrict__ cols = &d_col[(size_t)v * MAXDEG];

    float4 acc = *reinterpret_cast<const float4*>(&d_g[v * 64 + c0]);
    int j = 0;
    for (; j + 4 <= deg; j += 4) {
        int4 c4 = *reinterpret_cast<const int4*>(&cols[j]);
        float4 t0 = *reinterpret_cast<const float4*>(&d_g[c4.x * 64 + c0]);
        float4 t1 = *reinterpret_cast<const float4*>(&d_g[c4.y * 64 + c0]);
        float4 t2 = *reinterpret_cast<const float4*>(&d_g[c4.z * 64 + c0]);
        float4 t3 = *reinterpret_cast<const float4*>(&d_g[c4.w * 64 + c0]);
        acc.x += (t0.x + t1.x) + (t2.x + t3.x);
        acc.y += (t0.y + t1.y) + (t2.y + t3.y);
        acc.z += (t0.z + t1.z) + (t2.z + t3.z);
        acc.w += (t0.w + t1.w) + (t2.w + t3.w);
    }
    for (; j < deg; ++j) {
        int u = cols[j];
        float4 t = *reinterpret_cast<const float4*>(&d_g[u * 64 + c0]);
        acc.x += t.x; acc.y += t.y; acc.z += t.z; acc.w += t.w;
    }

    float4 b4 = *reinterpret_cast<const float4*>(&bias[c0]);
    float o0 = fmaxf(fmaf(dv, acc.x, b4.x), 0.0f);
    float o1 = fmaxf(fmaf(dv, acc.y, b4.y), 0.0f);
    float o2 = fmaxf(fmaf(dv, acc.z, b4.z), 0.0f);
    float o3 = fmaxf(fmaf(dv, acc.w, b4.w), 0.0f);

    unsigned i0 = (unsigned)v * 64u + (unsigned)c0;
    const float inv_keep = 1.0f / 0.7f;
    float h0 = keep_elem(k0, k1, i0)      ? o0 * inv_keep : 0.0f;
    float h1 = keep_elem(k0, k1, i0 + 1u) ? o1 * inv_keep : 0.0f;
    float h2 = keep_elem(k0, k1, i0 + 2u) ? o2 * inv_keep : 0.0f;
    float h3 = keep_elem(k0, k1, i0 + 3u) ? o3 * inv_keep : 0.0f;

    int g = batch[v];
    int gA = gAB[0], gB = gAB[1];
    if (g == gA) {
        atomicAdd(&accA[c0],     h0); atomicAdd(&accA[c0 + 1], h1);
        atomicAdd(&accA[c0 + 2], h2); atomicAdd(&accA[c0 + 3], h3);
    } else if (g == gB) {
        atomicAdd(&accB[c0],     h0); atomicAdd(&accB[c0 + 1], h1);
        atomicAdd(&accB[c0 + 2], h2); atomicAdd(&accB[c0 + 3], h3);
    } else {
        atomicAdd(&d_pooled[g * 64 + c0],     h0);
        atomicAdd(&d_pooled[g * 64 + c0 + 1], h1);
        atomicAdd(&d_pooled[g * 64 + c0 + 2], h2);
        atomicAdd(&d_pooled[g * 64 + c0 + 3], h3);
    }
    __syncthreads();
    if (tid < 64) atomicAdd(&d_pooled[gA * 64 + tid], accA[tid]);
    else if (tid < 128 && gAB[1] != gAB[0])
        atomicAdd(&d_pooled[gAB[1] * 64 + (tid - 64)], accB[tid - 64]);
}

// ---------------- MLP head: normalize sums -> means, then Linear stack -------
__global__ void k_head(const int* __restrict__ batch,
                       const float* __restrict__ Wm1, const float* __restrict__ bm1,
                       const float* __restrict__ Wm2, const float* __restrict__ bm2,
                       float* __restrict__ out, unsigned k0, unsigned k1) {
    __shared__ float Ps[64][64];
    __shared__ float Ws[64][64];
    __shared__ int   se[65];
    int tid = threadIdx.x;
    if (tid <= 64) {
        int target = tid;
        int lo = 0, hi = N_NODES;
        while (lo < hi) { int m = (lo + hi) >> 1; if (batch[m] < target) lo = m + 1; else hi = m; }
        se[tid] = lo;
    }
    for (int idx = tid; idx < 4096; idx += 1024)
        Ps[idx >> 6][idx & 63] = d_pooled[idx];
    for (int idx = tid; idx < 4096; idx += 1024)
        Ws[idx >> 6][idx & 63] = Wm1[idx];
    __syncthreads();
    for (int idx = tid; idx < 4096; idx += 1024) {
        int g = idx >> 6;
        float cnt = fmaxf((float)(se[g + 1] - se[g]), 1.0f);
        Ps[g][idx & 63] *= (1.0f / cnt);
    }
    __syncthreads();

    int c = tid & 63, gb = tid >> 6;
    float mv[2][2];
#pragma unroll
    for (int halfg = 0; halfg < 2; ++halfg) {
        int g = gb + halfg * 16;
        float mA = bm1[c], mB = bm1[c];
#pragma unroll
        for (int s = 0; s < 64; s++) {
            mA = fmaf(Ps[g][s], Ws[s][c], mA);
            mB = fmaf(Ps[g + 32][s], Ws[s][c], mB);
        }
        mA = fmaxf(mA, 0.0f);
        mB = fmaxf(mB, 0.0f);
        unsigned iA = (unsigned)g * 64u + (unsigned)c;
        unsigned iB = (unsigned)(g + 32) * 64u + (unsigned)c;
        const float inv_keep = 1.0f / 0.7f;
        mv[halfg][0] = keep_elem(k0, k1, iA) ? mA * inv_keep : 0.0f;
        mv[halfg][1] = keep_elem(k0, k1, iB) ? mB * inv_keep : 0.0f;
    }
    __syncthreads();
#pragma unroll
    for (int halfg = 0; halfg < 2; ++halfg) {
        int g = gb + halfg * 16;
        Ps[g][c] = mv[halfg][0];
        Ps[g + 32][c] = mv[halfg][1];
    }
    __syncthreads();
    if (tid < 64) {
        float o = bm2[0];
#pragma unroll
        for (int cc = 0; cc < 64; ++cc) o = fmaf(Ps[tid][cc], Wm2[cc], o);
        out[tid] = o;
    }
}

// ---------------- host threefry (key splitting) ----------------
static inline void tf_host(unsigned k0, unsigned k1, unsigned c0, unsigned c1,
                           unsigned& o0, unsigned& o1) {
    unsigned ks2 = k0 ^ k1 ^ 0x1BD11BDAu;
    unsigned x0 = c0 + k0, x1 = c1 + k1;
#define HROT(x, r) (((x) << (r)) | ((x) >> (32 - (r))))
#define HRND(r) { x0 += x1; x1 = HROT(x1, r); x1 ^= x0; }
    HRND(13) HRND(15) HRND(26) HRND(6)   x0 += k1;  x1 += ks2 + 1u;
    HRND(17) HRND(29) HRND(16) HRND(24)  x0 += ks2; x1 += k0 + 2u;
    HRND(13) HRND(15) HRND(26) HRND(6)   x0 += k0;  x1 += k1 + 3u;
    HRND(17) HRND(29) HRND(16) HRND(24)  x0 += k1;  x1 += ks2 + 4u;
    HRND(13) HRND(15) HRND(26) HRND(6)   x0 += ks2; x1 += k0 + 5u;
#undef HRND
#undef HROT
    o0 = x0; o1 = x1;
}

extern "C" void kernel_launch(void* const* d_in, const int* in_sizes, int n_in,
                              void* d_out, int out_size) {
    const float* x     = (const float*)d_in[0];
    const int*   ei    = (const int*)d_in[1];
    const int*   batch = (const int*)d_in[2];
    const float* W1 = (const float*)d_in[3];  const float* b1 = (const float*)d_in[4];
    const float* W2 = (const float*)d_in[5];  const float* b2 = (const float*)d_in[6];
    const float* W3 = (const float*)d_in[7];  const float* b3 = (const float*)d_in[8];
    const float* Wm1 = (const float*)d_in[9]; const float* bm1 = (const float*)d_in[10];
    const float* Wm2 = (const float*)d_in[11];const float* bm2 = (const float*)d_in[12];
    float* out = (float*)d_out;

    // split(key(42), 4) partitionable: dk[i] = threefry((0,42), (0, i))
    unsigned dk[4][2];
    for (unsigned i = 0; i < 4; i++)
        tf_host(0u, 42u, 0u, i, dk[i][0], dk[i][1]);

    static cudaStream_t s_csr = nullptr;
    static cudaEvent_t ev_root = nullptr, ev_csr = nullptr;
    if (!s_csr) {
        cudaStreamCreateWithFlags(&s_csr, cudaStreamNonBlocking);
        cudaEventCreateWithFlags(&ev_root, cudaEventDisableTiming);
        cudaEventCreateWithFlags(&ev_csr, cudaEventDisableTiming);
    }

    const int NB64 = N_NODES / 64;                          // 1250
    const int AGG_BLOCKS = (N_NODES / 2 * 32 + 255) / 256;  // 5000

    cudaEventRecord(ev_root, (cudaStream_t)0);
    cudaStreamWaitEvent(s_csr, ev_root, 0);

    // Adjacency build + dinv precompute on side stream, overlapped with GEMM1.
    k_zero_cnt<<<(N_NODES + 255) / 256, 256, 0, s_csr>>>();
    k_scatter<<<(N_EDGES + 255) / 256, 256, 0, s_csr>>>(ei);
    k_dinv<<<(N_NODES + 255) / 256, 256, 0, s_csr>>>();
    cudaEventRecord(ev_csr, s_csr);

    k_gemm1<<<NB64, 128>>>(x, W1);

    cudaStreamWaitEvent((cudaStream_t)0, ev_csr, 0);

    k_agg<true><<<AGG_BLOCKS, 256>>>(b1, dk[0][0], dk[0][1]);
    k_gemm2<<<NB64, 128>>>(W2);
    k_agg<false><<<AGG_BLOCKS, 256>>>(b2, dk[1][0], dk[1][1]);
    k_gemm2<<<NB64, 128>>>(W3);
    k_aggpool<<<AGG_BLOCKS, 256>>>(b3, batch, dk[2][0], dk[2][1]);

    k_head<<<1, 1024>>>(batch, Wm1, bm1, Wm2, bm2, out, dk[3][0], dk[3][1]);

    (void)in_sizes; (void)n_in; (void)out_size;
}